// round 5
// baseline (speedup 1.0000x reference)
#include <cuda_runtime.h>

// SpikingLayer: truncated-IIR EPSP (K=100, diff of exponentials) + spike/reset scan.
// T=1024, 4 balanced segments/row (14/6/6/6 output chunks; segs 1-3 prepend a
// 224-step burn-in: s-state exact after 100 steps, r residual ~8e-6).
// s1/s2 are carried as one packed f32x2 (sm_100 packed FP32 ops); lag-100
// corrections {c1,c2} applied as one predicated packed add.

#define T_LEN   1024
#define ROWS_PB 32
#define BSTR    33         // padded word stride per row (conflict-free)
#define THREADS 128        // 4 warps: warp w == segment w
#define BURN_CH 7          // 224-step burn-in

// packed f32x2 helpers (sm_100+)
#define MUL_F32X2(d, a, b) \
    asm("mul.rn.f32x2 %0, %1, %2;" : "=l"(d) : "l"(a), "l"(b))
#define PADD_F32X2(s, bit, cst) \
    asm("{\n\t.reg .pred p;\n\tsetp.ne.u32 p, %1, 0;\n\t" \
        "@p add.rn.f32x2 %0, %0, %2;\n\t}" \
        : "+l"(s) : "r"(bit), "l"(cst))

__device__ __forceinline__ unsigned long long pack2(float lo, float hi) {
    unsigned long long d;
    asm("mov.b64 %0, {%1, %2};" : "=l"(d)
        : "r"(__float_as_uint(lo)), "r"(__float_as_uint(hi)));
    return d;
}
__device__ __forceinline__ void unpack2(float& lo, float& hi, unsigned long long s) {
    unsigned a, b;
    asm("mov.b64 {%0, %1}, %2;" : "=r"(a), "=r"(b) : "l"(s));
    lo = __uint_as_float(a); hi = __uint_as_float(b);
}

__global__ __launch_bounds__(THREADS, 8)
void snn_kernel(const float* __restrict__ x,
                const float* __restrict__ rk,
                float* __restrict__ out)
{
    __shared__ unsigned sbits[ROWS_PB * BSTR];            // 4.2 KB input bitmap
    __shared__ float    tstage[4][ROWS_PB * BSTR];        // 16.9 KB out staging

    const int tid     = threadIdx.x;
    const int lane    = tid & 31;
    const int wid     = tid >> 5;
    const int rowbase = blockIdx.x * ROWS_PB;

    // ---------------- phase 1: load rows once (coalesced), pack to bits via shfl-OR
    #pragma unroll
    for (int i = 0; i < 8; ++i) {
        const int row = wid * 8 + i;
        const float4* p = reinterpret_cast<const float4*>(
            x + (size_t)(rowbase + row) * T_LEN);
        #pragma unroll
        for (int b = 0; b < 8; ++b) {
            const float4 v = p[b * 32 + lane];
            unsigned nib = (unsigned)(v.x != 0.f)
                         | ((unsigned)(v.y != 0.f) << 1)
                         | ((unsigned)(v.z != 0.f) << 2)
                         | ((unsigned)(v.w != 0.f) << 3);
            unsigned val = nib << ((lane & 7) * 4);
            val |= __shfl_xor_sync(0xffffffffu, val, 1);
            val |= __shfl_xor_sync(0xffffffffu, val, 2);
            val |= __shfl_xor_sync(0xffffffffu, val, 4);
            if ((lane & 7) == 0)
                sbits[row * BSTR + b * 4 + (lane >> 3)] = val;
        }
    }
    __syncthreads();

    // ---------------- phase 2: per-(row,segment) scan
    const float alpha = rk[1] / rk[0];                    // e^{-0.1} as reference computes
    const unsigned long long a12  = pack2(0.90483741803595952f,   // {a1, a2}
                                          0.81873075307798186f);
    const unsigned long long ones = pack2(1.0f, 1.0f);
    const unsigned long long negc = pack2(-4.5399929762484854e-05f,  // {-c1, -c2}
                                          -2.0611536224385578e-09f);

    // balanced output ranges (chunks of 32 steps): 14 / 6 / 6 / 6
    const int OUT0[4] = { 0, 14, 20, 26 };
    const int OUT1[4] = { 14, 20, 26, 32 };

    const int row = lane;
    const int seg = wid;
    const unsigned* __restrict__ mb = &sbits[row * BSTR];
    float* __restrict__ mo = &tstage[seg][row * BSTR];

    const int cout0 = OUT0[seg];
    const int cout1 = OUT1[seg];
    int c = (seg == 0) ? 0 : cout0 - BURN_CH;             // 224-step burn-in

    // sliding history of bit-words (for the lag-100 term)
    unsigned h1 = (c >= 1) ? mb[c - 1] : 0u;
    unsigned h2 = (c >= 2) ? mb[c - 2] : 0u;
    unsigned h3 = (c >= 3) ? mb[c - 3] : 0u;
    unsigned h4 = (c >= 4) ? mb[c - 4] : 0u;

    unsigned long long s12 = 0ull;                        // {s1, s2}
    float r = 0.f;

    // ---- burn-in chunks (discard output)
    for (; c < cout0; ++c) {
        const unsigned w  = mb[c];
        const unsigned lg = __funnelshift_r(h4, h3, 28);  // bits of x[t-100]
        #pragma unroll
        for (int j = 0; j < 32; ++j) {
            MUL_F32X2(s12, s12, a12);
            PADD_F32X2(s12, w  & (1u << j), ones);
            PADD_F32X2(s12, lg & (1u << j), negc);
            float s1, s2; unpack2(s1, s2, s12);
            const float v = (s1 - s2) - r;
            const float n = fmaxf(floorf(v), 0.0f);
            r = fmaf(n, alpha, r * alpha);
        }
        h4 = h3; h3 = h2; h2 = h1; h1 = w;
    }

    // ---- output chunks
    for (; c < cout1; ++c) {
        const unsigned w  = mb[c];
        const unsigned lg = __funnelshift_r(h4, h3, 28);
        #pragma unroll
        for (int j = 0; j < 32; ++j) {
            MUL_F32X2(s12, s12, a12);
            PADD_F32X2(s12, w  & (1u << j), ones);
            PADD_F32X2(s12, lg & (1u << j), negc);
            float s1, s2; unpack2(s1, s2, s12);
            const float v = (s1 - s2) - r;
            const float n = fmaxf(floorf(v), 0.0f);
            r = fmaf(n, alpha, r * alpha);
            mo[j] = n;
        }
        h4 = h3; h3 = h2; h2 = h1; h1 = w;
        __syncwarp();
        #pragma unroll
        for (int k = 0; k < 8; ++k) {                     // 32 rows x 128B, coalesced
            const int f  = lane + k * 32;
            const int rr = f >> 3;
            const int jj = (f & 7) * 4;
            const float* sp = &tstage[seg][rr * BSTR + jj];
            const float4 v4 = make_float4(sp[0], sp[1], sp[2], sp[3]);
            *reinterpret_cast<float4*>(
                out + (size_t)(rowbase + rr) * T_LEN + c * 32 + jj) = v4;
        }
        __syncwarp();
    }
}

extern "C" void kernel_launch(void* const* d_in, const int* in_sizes, int n_in,
                              void* d_out, int out_size)
{
    const float* x  = (const float*)d_in[0];   // binary_input (1,32,1024,1024)
    const float* rk = (const float*)d_in[2];   // ref_kernel (alpha source)
    float* out = (float*)d_out;                // (32,1024,1024) float32

    const int rows = out_size / T_LEN;         // 32768
    snn_kernel<<<rows / ROWS_PB, THREADS>>>(x, rk, out);
    (void)in_sizes; (void)n_in;
}

// round 6
// speedup vs baseline: 1.1100x; 1.1100x over previous
#include <cuda_runtime.h>

// SpikingLayer: truncated-IIR EPSP (K=100, diff of exponentials) + spike/reset scan.
// T=1024, 4 balanced segments/row (14/6/6/6 output chunks; segs 1-3 prepend a
// 224-step burn-in: s-state exact after 100 steps, r residual ~1e-5 decayed).
// Scalar fmaf recursion (bit-stable, rel_err 0.0 in R2/R4). Output staged through
// 16B-aligned float4 shared tiles (stride 9 float4 = conflict-free) so all
// shared/global traffic is 128-bit.

#define T_LEN   1024
#define ROWS_PB 32
#define BSTR    33         // bitmap word stride per row (conflict-free)
#define FSTR    9          // staging stride in float4 units (36B, conflict-free)
#define THREADS 128        // 4 warps: warp w == segment w
#define BURN_CH 7          // 224-step burn-in (validated rel_err 0.0)

__global__ __launch_bounds__(THREADS, 8)
void snn_kernel(const float* __restrict__ x,
                const float* __restrict__ rk,
                float* __restrict__ out)
{
    __shared__ unsigned sbits[ROWS_PB * BSTR];            // 4.2 KB input bitmap
    __shared__ float4   tstage[4][ROWS_PB * FSTR];        // 18.4 KB out staging

    const int tid     = threadIdx.x;
    const int lane    = tid & 31;
    const int wid     = tid >> 5;
    const int rowbase = blockIdx.x * ROWS_PB;

    // ---------------- phase 1: load rows once (coalesced), pack to bits via shfl-OR
    #pragma unroll
    for (int i = 0; i < 8; ++i) {
        const int row = wid * 8 + i;
        const float4* p = reinterpret_cast<const float4*>(
            x + (size_t)(rowbase + row) * T_LEN);
        #pragma unroll
        for (int b = 0; b < 8; ++b) {
            const float4 v = p[b * 32 + lane];
            unsigned nib = (unsigned)(v.x != 0.f)
                         | ((unsigned)(v.y != 0.f) << 1)
                         | ((unsigned)(v.z != 0.f) << 2)
                         | ((unsigned)(v.w != 0.f) << 3);
            unsigned val = nib << ((lane & 7) * 4);
            val |= __shfl_xor_sync(0xffffffffu, val, 1);
            val |= __shfl_xor_sync(0xffffffffu, val, 2);
            val |= __shfl_xor_sync(0xffffffffu, val, 4);
            if ((lane & 7) == 0)
                sbits[row * BSTR + b * 4 + (lane >> 3)] = val;
        }
    }
    __syncthreads();

    // ---------------- phase 2: per-(row,segment) scan
    const float alpha = rk[1] / rk[0];                    // e^{-0.1} as reference computes
    const float a1 = 0.90483741803595952f;                // exp(-0.1)
    const float a2 = 0.81873075307798186f;                // exp(-0.2)
    const float c1 = 4.5399929762484854e-05f;             // exp(-10) = a1^100
    // c2 = exp(-20) ~ 2e-9 is below s2's ulp -> dropped (deviation <= 1e-8)

    // balanced output ranges (chunks of 32 steps): 14 / 6 / 6 / 6
    const int OUT0[4] = { 0, 14, 20, 26 };
    const int OUT1[4] = { 14, 20, 26, 32 };

    const int row = lane;
    const int seg = wid;
    const unsigned* __restrict__ mb = &sbits[row * BSTR];
    float4* __restrict__ mo = &tstage[seg][row * FSTR];

    const int cout0 = OUT0[seg];
    const int cout1 = OUT1[seg];
    int c = (seg == 0) ? 0 : cout0 - BURN_CH;             // 224-step burn-in

    // sliding history of bit-words (for the lag-100 term)
    unsigned h1 = (c >= 1) ? mb[c - 1] : 0u;
    unsigned h2 = (c >= 2) ? mb[c - 2] : 0u;
    unsigned h3 = (c >= 3) ? mb[c - 3] : 0u;
    unsigned h4 = (c >= 4) ? mb[c - 4] : 0u;

    float s1 = 0.f, s2 = 0.f, r = 0.f;

    // ---- burn-in chunks (discard output); s-state exact after 100 steps
    for (; c < cout0; ++c) {
        const unsigned w  = mb[c];
        const unsigned lg = __funnelshift_r(h4, h3, 28);  // bits of x[t-100]
        #pragma unroll
        for (int j = 0; j < 32; ++j) {
            const float xf = (w >> j & 1u) ? 1.0f : 0.0f;
            s1 = fmaf(a1, s1, xf);
            s2 = fmaf(a2, s2, xf);
            if (lg >> j & 1u) s1 -= c1;
            const float v = (s1 - s2) - r;
            const float n = fmaxf(floorf(v), 0.0f);
            r = fmaf(n, alpha, r * alpha);
        }
        h4 = h3; h3 = h2; h2 = h1; h1 = w;
    }

    // ---- output chunks: accumulate 4 steps into a float4, STS.128 every 4 steps
    for (; c < cout1; ++c) {
        const unsigned w  = mb[c];
        const unsigned lg = __funnelshift_r(h4, h3, 28);
        float4 acc;
        #pragma unroll
        for (int j = 0; j < 32; ++j) {
            const float xf = (w >> j & 1u) ? 1.0f : 0.0f;
            s1 = fmaf(a1, s1, xf);
            s2 = fmaf(a2, s2, xf);
            if (lg >> j & 1u) s1 -= c1;
            const float v = (s1 - s2) - r;
            const float n = fmaxf(floorf(v), 0.0f);
            r = fmaf(n, alpha, r * alpha);
            // j is a compile-time constant (full unroll): resolves to registers
            if ((j & 3) == 0) acc.x = n;
            else if ((j & 3) == 1) acc.y = n;
            else if ((j & 3) == 2) acc.z = n;
            else { acc.w = n; mo[j >> 2] = acc; }
        }
        h4 = h3; h3 = h2; h2 = h1; h1 = w;
        __syncwarp();
        // transpose-store: 8 x (LDS.128 + STG.128), fully coalesced
        #pragma unroll
        for (int k = 0; k < 8; ++k) {
            const int f  = lane + k * 32;
            const int rr = f >> 3;          // row 0..31
            const int jq = f & 7;           // float4 index 0..7 within chunk
            const float4 v4 = tstage[seg][rr * FSTR + jq];
            *reinterpret_cast<float4*>(
                out + (size_t)(rowbase + rr) * T_LEN + c * 32 + jq * 4) = v4;
        }
        __syncwarp();
    }
}

extern "C" void kernel_launch(void* const* d_in, const int* in_sizes, int n_in,
                              void* d_out, int out_size)
{
    const float* x  = (const float*)d_in[0];   // binary_input (1,32,1024,1024)
    const float* rk = (const float*)d_in[2];   // ref_kernel (alpha source)
    float* out = (float*)d_out;                // (32,1024,1024) float32

    const int rows = out_size / T_LEN;         // 32768
    snn_kernel<<<rows / ROWS_PB, THREADS>>>(x, rk, out);
    (void)in_sizes; (void)n_in;
}